// round 15
// baseline (speedup 1.0000x reference)
#include <cuda_runtime.h>
#include <cuda_bf16.h>

// ---------------------------------------------------------------------------
// QCNNHybrid R14 (stats/fold = R10 exact, the 49.9us components):
//  k_stats : 512 CTAs x 4 chunks of 16KB, double-buffered cp.async.bulk.
//  k_fold  : 1 block; reduce 512 partials, fold BN, write g_w (layout B).
//  memcpy  : g_w -> __constant__ c_w (graph node).
//  k_main  : NEW: 4 rows/thread but SEQUENTIAL packs per layer -> peak
//            activation liveness 48 u64 (not 64) -> launch_bounds(128,4)
//            fits ~128 regs without spills -> 16 warps/SM.
// ---------------------------------------------------------------------------

#define ST_GRID    512
#define ST_CHUNKS  4
#define NT_STATS   256
#define NT_MAIN    128

__device__ float g_partials[ST_GRID * 16];

// layout B (u64 units): per layer [bias x DOUT][weights j-major: DOUT x DIN]
#define FM_B 0
#define FM_W 16     // 16 + 128 = 144
#define C1_B 144
#define C1_W 160    // + 256 = 416
#define P1_B 416
#define P1_W 428    // + 192 = 620
#define C2_B 620
#define C2_W 628    // + 96 = 724
#define P2_B 724
#define P2_W 728    // + 32 = 760
#define C3_B 760
#define C3_W 764    // + 16 = 780
#define R_B  780
#define R_W  784    // + 16 = 800
#define H_B  800
#define H_W  801    // + 4 = 805
#define U_TOTAL 805
__device__ float2 g_w[U_TOTAL];
__constant__ __align__(16) float2 c_w[U_TOTAL + 1];

typedef unsigned long long u64;

// ------------------------------- f32x2 helpers -----------------------------
__device__ __forceinline__ u64 pk2(float a, float b) {
    u64 r;
    asm("mov.b64 %0,{%1,%2};" : "=l"(r) : "f"(a), "f"(b));
    return r;
}
__device__ __forceinline__ void upk2(u64 v, float& a, float& b) {
    asm("mov.b64 {%0,%1},%2;" : "=f"(a), "=f"(b) : "l"(v));
}
__device__ __forceinline__ u64 ffma2(u64 a, u64 b, u64 c) {
    u64 d;
    asm("fma.rn.f32x2 %0,%1,%2,%3;" : "=l"(d) : "l"(a), "l"(b), "l"(c));
    return d;
}
__device__ __forceinline__ u64 fadd2(u64 a, u64 b) {
    u64 d;
    asm("add.rn.f32x2 %0,%1,%2;" : "=l"(d) : "l"(a), "l"(b));
    return d;
}
__device__ __forceinline__ float tanh_ap(float x) {
    float y;
    asm("tanh.approx.f32 %0,%1;" : "=f"(y) : "f"(x));
    return y;
}
__device__ __forceinline__ u64 tanh2(u64 v) {
    float a, b;
    upk2(v, a, b);
    return pk2(tanh_ap(a), tanh_ap(b));
}
__device__ __forceinline__ u64 relu2(u64 v) {
    float a, b;
    upk2(v, a, b);
    return pk2(fmaxf(a, 0.0f), fmaxf(b, 0.0f));
}

// dense layer on ONE pack (2 rows); LDC.128 weight pairs from __constant__.
template <int DIN, int DOUT, int BB, int WB, bool ACT>
__device__ __forceinline__ void layerSP(const u64* __restrict__ a,
                                        u64* __restrict__ o) {
    const u64* cw = (const u64*)c_w;
#pragma unroll
    for (int j = 0; j < DOUT; j++) {
        u64 acc = cw[BB + j];                         // duplicated bias
#pragma unroll
        for (int i = 0; i < DIN; i += 2) {
            ulonglong2 w = *(const ulonglong2*)(cw + WB + j * DIN + i);
            acc = ffma2(a[i], w.x, acc);
            acc = ffma2(a[i + 1], w.y, acc);
        }
        if (ACT) acc = tanh2(acc);
        o[j] = acc;
    }
}

// ------------------------------- kernel A: stats ---------------------------
__global__ void __launch_bounds__(NT_STATS) k_stats(const float* __restrict__ x) {
    __shared__ __align__(16) float s_buf[2][4096];    // 2 x 16KB
    __shared__ __align__(8) u64 s_mbar[2];
    int tid = threadIdx.x;
    int cta = blockIdx.x;

    unsigned mb[2] = { (unsigned)__cvta_generic_to_shared(&s_mbar[0]),
                       (unsigned)__cvta_generic_to_shared(&s_mbar[1]) };
    unsigned sb[2] = { (unsigned)__cvta_generic_to_shared(s_buf[0]),
                       (unsigned)__cvta_generic_to_shared(s_buf[1]) };
    if (tid == 0) {
        asm volatile("mbarrier.init.shared.b64 [%0], 1;" :: "r"(mb[0]) : "memory");
        asm volatile("mbarrier.init.shared.b64 [%0], 1;" :: "r"(mb[1]) : "memory");
        asm volatile("fence.proxy.async.shared::cta;" ::: "memory");
    }
    __syncthreads();

#define ST_COPY(k)                                                             \
    do {                                                                       \
        int _b = (k) & 1;                                                      \
        const char* _src =                                                     \
            (const char*)x + ((size_t)cta * ST_CHUNKS + (k)) * 16384;          \
        asm volatile("mbarrier.arrive.expect_tx.shared.b64 _, [%0], %1;"       \
                     :: "r"(mb[_b]), "r"(16384u) : "memory");                  \
        asm volatile(                                                          \
            "cp.async.bulk.shared::cluster.global.mbarrier::complete_tx::bytes "\
            "[%0], [%1], %2, [%3];"                                            \
            :: "r"(sb[_b]), "l"(_src), "r"(16384u), "r"(mb[_b]) : "memory");   \
    } while (0)

    if (tid == 0) { ST_COPY(0); ST_COPY(1); }

    float s[8], q[8];
#pragma unroll
    for (int c = 0; c < 8; c++) { s[c] = 0.0f; q[c] = 0.0f; }

#pragma unroll
    for (int k = 0; k < ST_CHUNKS; k++) {
        int b = k & 1, parity = (k >> 1) & 1;
        asm volatile(
            "{\n\t"
            ".reg .pred p;\n\t"
            "WAITS_%=:\n\t"
            "mbarrier.try_wait.parity.acquire.cta.shared::cta.b64 p, [%0], %1;\n\t"
            "@!p bra WAITS_%=;\n\t"
            "}"
            :: "r"(mb[b]), "r"(parity) : "memory");
        const float4* sv = (const float4*)s_buf[b];
        float4 a0 = sv[tid * 2], b0 = sv[tid * 2 + 1];
        float4 a1 = sv[(tid + 256) * 2], b1 = sv[(tid + 256) * 2 + 1];
        s[0] += a0.x + a1.x; q[0] = fmaf(a0.x, a0.x, fmaf(a1.x, a1.x, q[0]));
        s[1] += a0.y + a1.y; q[1] = fmaf(a0.y, a0.y, fmaf(a1.y, a1.y, q[1]));
        s[2] += a0.z + a1.z; q[2] = fmaf(a0.z, a0.z, fmaf(a1.z, a1.z, q[2]));
        s[3] += a0.w + a1.w; q[3] = fmaf(a0.w, a0.w, fmaf(a1.w, a1.w, q[3]));
        s[4] += b0.x + b1.x; q[4] = fmaf(b0.x, b0.x, fmaf(b1.x, b1.x, q[4]));
        s[5] += b0.y + b1.y; q[5] = fmaf(b0.y, b0.y, fmaf(b1.y, b1.y, q[5]));
        s[6] += b0.z + b1.z; q[6] = fmaf(b0.z, b0.z, fmaf(b1.z, b1.z, q[6]));
        s[7] += b0.w + b1.w; q[7] = fmaf(b0.w, b0.w, fmaf(b1.w, b1.w, q[7]));
        __syncthreads();                               // buffer fully consumed
        if (tid == 0 && k + 2 < ST_CHUNKS) ST_COPY(k + 2);
    }

    // transpose-reduce (reuse the 32KB buffer area, rows of 264 floats)
    float* st = (float*)s_buf;
#pragma unroll
    for (int c = 0; c < 8; c++) {
        st[c * 264 + tid] = s[c];
        st[(8 + c) * 264 + tid] = q[c];
    }
    __syncthreads();
    {
        int w = tid >> 5, lane = tid & 31;
#pragma unroll
        for (int h = 0; h < 2; h++) {
            int c = 2 * w + h;
            const float4* row = (const float4*)(st + c * 264);
            float4 a = row[lane];
            float4 b = row[lane + 32];
            float p = ((a.x + a.y) + (a.z + a.w)) + ((b.x + b.y) + (b.z + b.w));
#pragma unroll
            for (int o = 16; o > 0; o >>= 1)
                p += __shfl_xor_sync(0xffffffffu, p, o);
            if (lane == 0) g_partials[cta * 16 + c] = p;
        }
    }
}

// ------------------------------- kernel B: fold ----------------------------
__global__ void __launch_bounds__(256) k_fold(
    const float* __restrict__ bn_g, const float* __restrict__ bn_b,
    const float* __restrict__ w_fm, const float* __restrict__ b_fm,
    const float* __restrict__ w_c1, const float* __restrict__ b_c1,
    const float* __restrict__ w_p1, const float* __restrict__ b_p1,
    const float* __restrict__ w_c2, const float* __restrict__ b_c2,
    const float* __restrict__ w_p2, const float* __restrict__ b_p2,
    const float* __restrict__ w_c3, const float* __restrict__ b_c3,
    const float* __restrict__ w_r,  const float* __restrict__ b_r,
    const float* __restrict__ w_h,  const float* __restrict__ b_h,
    float invB) {
    int tid = threadIdx.x;
    __shared__ float s1[256];
    __shared__ float totals[16];
    __shared__ float scale[8], shift[8];
    {   // 16 cols x 16 chunks of 32; 8 independent accumulators (MLP)
        int col = tid & 15, chunk = tid >> 4;
        const float* p = g_partials + (chunk * 32) * 16 + col;
        float a0 = 0, a1 = 0, a2 = 0, a3 = 0, a4 = 0, a5 = 0, a6 = 0, a7 = 0;
#pragma unroll
        for (int b = 0; b < 32; b += 8) {
            a0 += p[(b + 0) * 16]; a1 += p[(b + 1) * 16];
            a2 += p[(b + 2) * 16]; a3 += p[(b + 3) * 16];
            a4 += p[(b + 4) * 16]; a5 += p[(b + 5) * 16];
            a6 += p[(b + 6) * 16]; a7 += p[(b + 7) * 16];
        }
        s1[col * 16 + chunk] = ((a0 + a1) + (a2 + a3)) + ((a4 + a5) + (a6 + a7));
    }
    __syncthreads();
    if (tid < 16) {
        float acc = 0.0f;
#pragma unroll
        for (int k = 0; k < 16; k++) acc += s1[tid * 16 + k];
        totals[tid] = acc;
    }
    __syncthreads();
    if (tid < 8) {
        float mu = totals[tid] * invB;
        float var = totals[8 + tid] * invB - mu * mu;
        float sc = bn_g[tid] * rsqrtf(var + 1e-5f);
        scale[tid] = sc;
        shift[tid] = bn_b[tid] - mu * sc;
    }
    __syncthreads();

    // folded first layer, layout B
    if (tid < 16) {
        float v = b_fm[tid];
#pragma unroll
        for (int i = 0; i < 8; i++) v += shift[i] * w_fm[i * 16 + tid];
        g_w[FM_B + tid] = make_float2(v, v);
    }
    if (tid < 128) {
        int j = tid >> 3, i = tid & 7;
        float v = scale[i] * w_fm[i * 16 + j];
        g_w[FM_W + j * 8 + i] = make_float2(v, v);
    }
    for (int idx = tid; idx < 256; idx += 256) {       // c1 16->16
        int j = idx >> 4, i = idx & 15;
        float v = w_c1[i * 16 + j];
        g_w[C1_W + j * 16 + i] = make_float2(v, v);
    }
    if (tid < 16) { float v = b_c1[tid]; g_w[C1_B + tid] = make_float2(v, v); }
    if (tid < 192) {                                   // p1 16->12
        int j = tid >> 4, i = tid & 15;
        float v = w_p1[i * 12 + j];
        g_w[P1_W + j * 16 + i] = make_float2(v, v);
    }
    if (tid < 12) { float v = b_p1[tid]; g_w[P1_B + tid] = make_float2(v, v); }
    if (tid < 96) {                                    // c2 12->8
        int j = tid / 12, i = tid % 12;
        float v = w_c2[i * 8 + j];
        g_w[C2_W + j * 12 + i] = make_float2(v, v);
    }
    if (tid < 8) { float v = b_c2[tid]; g_w[C2_B + tid] = make_float2(v, v); }
    if (tid < 32) {                                    // p2 8->4
        int j = tid >> 3, i = tid & 7;
        float v = w_p2[i * 4 + j];
        g_w[P2_W + j * 8 + i] = make_float2(v, v);
    }
    if (tid < 4) { float v = b_p2[tid]; g_w[P2_B + tid] = make_float2(v, v); }
    if (tid < 16) {                                    // c3 4->4
        int j = tid >> 2, i = tid & 3;
        float v = w_c3[i * 4 + j];
        g_w[C3_W + j * 4 + i] = make_float2(v, v);
    }
    if (tid < 4) { float v = b_c3[tid]; g_w[C3_B + tid] = make_float2(v, v); }
    if (tid < 16) {                                    // r 4->4
        int j = tid >> 2, i = tid & 3;
        float v = w_r[i * 4 + j];
        g_w[R_W + j * 4 + i] = make_float2(v, v);
    }
    if (tid < 4) { float v = b_r[tid]; g_w[R_B + tid] = make_float2(v, v); }
    if (tid < 4) { float v = w_h[tid]; g_w[H_W + tid] = make_float2(v, v); }
    if (tid == 0) { float v = b_h[0]; g_w[H_B] = make_float2(v, v); }
}

// ------------------------------- kernel C: main ----------------------------
// 4 rows/thread, but each layer processes pack0 fully, then pack1 ->
// peak activation liveness 48 u64 instead of 64 -> occupancy 4 blocks/SM.
__global__ void __launch_bounds__(NT_MAIN, 4) k_main(const float* __restrict__ x,
                                                     float* __restrict__ out,
                                                     int nrows) {
    int t = blockIdx.x * NT_MAIN + threadIdx.x;
    long base = (long)t * 4;                          // 4 rows / thread
    if (base >= nrows) return;

    const float4* xv = (const float4*)(x + base * 8);
    float4 r0a = xv[0], r0b = xv[1];
    float4 r1a = xv[2], r1b = xv[3];
    float4 r2a = xv[4], r2b = xv[5];
    float4 r3a = xv[6], r3b = xv[7];

    u64 A0[16], A1[16], B0[16], B1[16];
    A0[0] = pk2(r0a.x, r1a.x); A1[0] = pk2(r2a.x, r3a.x);
    A0[1] = pk2(r0a.y, r1a.y); A1[1] = pk2(r2a.y, r3a.y);
    A0[2] = pk2(r0a.z, r1a.z); A1[2] = pk2(r2a.z, r3a.z);
    A0[3] = pk2(r0a.w, r1a.w); A1[3] = pk2(r2a.w, r3a.w);
    A0[4] = pk2(r0b.x, r1b.x); A1[4] = pk2(r2b.x, r3b.x);
    A0[5] = pk2(r0b.y, r1b.y); A1[5] = pk2(r2b.y, r3b.y);
    A0[6] = pk2(r0b.z, r1b.z); A1[6] = pk2(r2b.z, r3b.z);
    A0[7] = pk2(r0b.w, r1b.w); A1[7] = pk2(r2b.w, r3b.w);

    // feature_map (BN folded)
    layerSP<8, 16, FM_B, FM_W, true>(A0, B0);
    layerSP<8, 16, FM_B, FM_W, true>(A1, B1);
    // conv1
    layerSP<16, 16, C1_B, C1_W, true>(B0, A0);
    layerSP<16, 16, C1_B, C1_W, true>(B1, A1);
    // pool1
    layerSP<16, 12, P1_B, P1_W, true>(A0, B0);
    layerSP<16, 12, P1_B, P1_W, true>(A1, B1);
    // conv2
    layerSP<12, 8, C2_B, C2_W, true>(B0, A0);
    layerSP<12, 8, C2_B, C2_W, true>(B1, A1);
    // pool2
    layerSP<8, 4, P2_B, P2_W, true>(A0, B0);
    layerSP<8, 4, P2_B, P2_W, true>(A1, B1);
    // conv3
    layerSP<4, 4, C3_B, C3_W, true>(B0, A0);
    layerSP<4, 4, C3_B, C3_W, true>(B1, A1);
    // residual pre-relu
    layerSP<4, 4, R_B, R_W, false>(A0, B0);
    layerSP<4, 4, R_B, R_W, false>(A1, B1);
#pragma unroll
    for (int j = 0; j < 4; j++) {
        A0[j] = fadd2(A0[j], relu2(B0[j]));
        A1[j] = fadd2(A1[j], relu2(B1[j]));
    }

    // head [4->1], sigmoid(z) = 0.5*tanh(0.5z)+0.5
    const u64* cw = (const u64*)c_w;
    u64 acc0 = cw[H_B], acc1 = acc0;
#pragma unroll
    for (int i = 0; i < 4; i++) {
        u64 w = cw[H_W + i];
        acc0 = ffma2(A0[i], w, acc0);
        acc1 = ffma2(A1[i], w, acc1);
    }
    float z0, z1, z2, z3;
    upk2(acc0, z0, z1);
    upk2(acc1, z2, z3);
    float4 o;
    o.x = fmaf(0.5f, tanh_ap(0.5f * z0), 0.5f);
    o.y = fmaf(0.5f, tanh_ap(0.5f * z1), 0.5f);
    o.z = fmaf(0.5f, tanh_ap(0.5f * z2), 0.5f);
    o.w = fmaf(0.5f, tanh_ap(0.5f * z3), 0.5f);
    ((float4*)out)[t] = o;
}

// ------------------------------- launch ------------------------------------
extern "C" void kernel_launch(void* const* d_in, const int* in_sizes, int n_in,
                              void* d_out, int out_size) {
    const float* x    = (const float*)d_in[0];
    const float* bn_g = (const float*)d_in[1];
    const float* bn_b = (const float*)d_in[2];
    const float* w_fm = (const float*)d_in[3];
    const float* b_fm = (const float*)d_in[4];
    const float* w_c1 = (const float*)d_in[5];
    const float* b_c1 = (const float*)d_in[6];
    const float* w_p1 = (const float*)d_in[7];
    const float* b_p1 = (const float*)d_in[8];
    const float* w_c2 = (const float*)d_in[9];
    const float* b_c2 = (const float*)d_in[10];
    const float* w_p2 = (const float*)d_in[11];
    const float* b_p2 = (const float*)d_in[12];
    const float* w_c3 = (const float*)d_in[13];
    const float* b_c3 = (const float*)d_in[14];
    const float* w_r  = (const float*)d_in[15];
    const float* b_r  = (const float*)d_in[16];
    const float* w_h  = (const float*)d_in[17];
    const float* b_h  = (const float*)d_in[18];
    float* out = (float*)d_out;

    int nrows = in_sizes[0] / 8;                      // 1048576

    k_stats<<<ST_GRID, NT_STATS>>>(x);
    k_fold<<<1, 256>>>(bn_g, bn_b, w_fm, b_fm, w_c1, b_c1, w_p1, b_p1,
                       w_c2, b_c2, w_p2, b_p2, w_c3, b_c3, w_r, b_r,
                       w_h, b_h, 1.0f / (float)nrows);
    void* gw_addr = nullptr;
    cudaGetSymbolAddress(&gw_addr, g_w);
    cudaMemcpyToSymbolAsync(c_w, gw_addr, U_TOTAL * sizeof(float2), 0,
                            cudaMemcpyDeviceToDevice, 0);
    k_main<<<(nrows / 4) / NT_MAIN, NT_MAIN>>>(x, out, nrows);
}

// round 16
// speedup vs baseline: 1.0797x; 1.0797x over previous
#include <cuda_runtime.h>
#include <cuda_bf16.h>

// ---------------------------------------------------------------------------
// QCNNHybrid R15 (= R10, the 49.9us config, with fold merged into k_stats):
//  k_statsfold : 512 CTAs x 4 chunks of 16KB, double-buffered cp.async.bulk;
//                SMEM-transpose reduction; LAST CTA (ticket) reduces the 512
//                partials, folds BN into layer-1, writes g_w (layout B).
//  memcpy      : g_w -> __constant__ c_w (graph node).
//  k_main      : FROZEN R10 core (2 packs / 4 rows, LDC.128 weight pairs,
//                164 regs, 3 blocks/SM). Byte-identical to R10.
// ---------------------------------------------------------------------------

#define ST_GRID    512
#define ST_CHUNKS  4
#define NT_STATS   256
#define NT_MAIN    128

__device__ float g_partials[ST_GRID * 16];
__device__ unsigned int g_ticket;    // zero-init; self-resets each replay

// layout B (u64 units): per layer [bias x DOUT][weights j-major: DOUT x DIN]
#define FM_B 0
#define FM_W 16     // 16 + 128 = 144
#define C1_B 144
#define C1_W 160    // + 256 = 416
#define P1_B 416
#define P1_W 428    // + 192 = 620
#define C2_B 620
#define C2_W 628    // + 96 = 724
#define P2_B 724
#define P2_W 728    // + 32 = 760
#define C3_B 760
#define C3_W 764    // + 16 = 780
#define R_B  780
#define R_W  784    // + 16 = 800
#define H_B  800
#define H_W  801    // + 4 = 805
#define U_TOTAL 805
__device__ float2 g_w[U_TOTAL];
__constant__ __align__(16) float2 c_w[U_TOTAL + 1];

typedef unsigned long long u64;

// ------------------------------- f32x2 helpers -----------------------------
__device__ __forceinline__ u64 pk2(float a, float b) {
    u64 r;
    asm("mov.b64 %0,{%1,%2};" : "=l"(r) : "f"(a), "f"(b));
    return r;
}
__device__ __forceinline__ void upk2(u64 v, float& a, float& b) {
    asm("mov.b64 {%0,%1},%2;" : "=f"(a), "=f"(b) : "l"(v));
}
__device__ __forceinline__ u64 ffma2(u64 a, u64 b, u64 c) {
    u64 d;
    asm("fma.rn.f32x2 %0,%1,%2,%3;" : "=l"(d) : "l"(a), "l"(b), "l"(c));
    return d;
}
__device__ __forceinline__ u64 fadd2(u64 a, u64 b) {
    u64 d;
    asm("add.rn.f32x2 %0,%1,%2;" : "=l"(d) : "l"(a), "l"(b));
    return d;
}
__device__ __forceinline__ float tanh_ap(float x) {
    float y;
    asm("tanh.approx.f32 %0,%1;" : "=f"(y) : "f"(x));
    return y;
}
__device__ __forceinline__ u64 tanh2(u64 v) {
    float a, b;
    upk2(v, a, b);
    return pk2(tanh_ap(a), tanh_ap(b));
}
__device__ __forceinline__ u64 relu2(u64 v) {
    float a, b;
    upk2(v, a, b);
    return pk2(fmaxf(a, 0.0f), fmaxf(b, 0.0f));
}

// dense layer on two packs (4 rows); weights via vectorized constant loads.
template <int DIN, int DOUT, int BB, int WB, bool ACT>
__device__ __forceinline__ void layer2C(const u64* __restrict__ a0,
                                        const u64* __restrict__ a1,
                                        u64* __restrict__ o0,
                                        u64* __restrict__ o1) {
    const u64* cw = (const u64*)c_w;
#pragma unroll
    for (int j = 0; j < DOUT; j++) {
        u64 acc0 = cw[BB + j];                        // duplicated bias
        u64 acc1 = acc0;
#pragma unroll
        for (int i = 0; i < DIN; i += 2) {
            ulonglong2 w = *(const ulonglong2*)(cw + WB + j * DIN + i);
            acc0 = ffma2(a0[i], w.x, acc0);
            acc1 = ffma2(a1[i], w.x, acc1);
            acc0 = ffma2(a0[i + 1], w.y, acc0);
            acc1 = ffma2(a1[i + 1], w.y, acc1);
        }
        if (ACT) { acc0 = tanh2(acc0); acc1 = tanh2(acc1); }
        o0[j] = acc0;
        o1[j] = acc1;
    }
}

// --------------------------- kernel A: stats + fold ------------------------
__global__ void __launch_bounds__(NT_STATS) k_statsfold(
    const float* __restrict__ x,
    const float* __restrict__ bn_g, const float* __restrict__ bn_b,
    const float* __restrict__ w_fm, const float* __restrict__ b_fm,
    const float* __restrict__ w_c1, const float* __restrict__ b_c1,
    const float* __restrict__ w_p1, const float* __restrict__ b_p1,
    const float* __restrict__ w_c2, const float* __restrict__ b_c2,
    const float* __restrict__ w_p2, const float* __restrict__ b_p2,
    const float* __restrict__ w_c3, const float* __restrict__ b_c3,
    const float* __restrict__ w_r,  const float* __restrict__ b_r,
    const float* __restrict__ w_h,  const float* __restrict__ b_h,
    float invB) {
    __shared__ __align__(16) float s_buf[2][4096];    // 2 x 16KB
    __shared__ __align__(8) u64 s_mbar[2];
    int tid = threadIdx.x;
    int cta = blockIdx.x;

    unsigned mb[2] = { (unsigned)__cvta_generic_to_shared(&s_mbar[0]),
                       (unsigned)__cvta_generic_to_shared(&s_mbar[1]) };
    unsigned sb[2] = { (unsigned)__cvta_generic_to_shared(s_buf[0]),
                       (unsigned)__cvta_generic_to_shared(s_buf[1]) };
    if (tid == 0) {
        asm volatile("mbarrier.init.shared.b64 [%0], 1;" :: "r"(mb[0]) : "memory");
        asm volatile("mbarrier.init.shared.b64 [%0], 1;" :: "r"(mb[1]) : "memory");
        asm volatile("fence.proxy.async.shared::cta;" ::: "memory");
    }
    __syncthreads();

#define ST_COPY(k)                                                             \
    do {                                                                       \
        int _b = (k) & 1;                                                      \
        const char* _src =                                                     \
            (const char*)x + ((size_t)cta * ST_CHUNKS + (k)) * 16384;          \
        asm volatile("mbarrier.arrive.expect_tx.shared.b64 _, [%0], %1;"       \
                     :: "r"(mb[_b]), "r"(16384u) : "memory");                  \
        asm volatile(                                                          \
            "cp.async.bulk.shared::cluster.global.mbarrier::complete_tx::bytes "\
            "[%0], [%1], %2, [%3];"                                            \
            :: "r"(sb[_b]), "l"(_src), "r"(16384u), "r"(mb[_b]) : "memory");   \
    } while (0)

    if (tid == 0) { ST_COPY(0); ST_COPY(1); }

    float s[8], q[8];
#pragma unroll
    for (int c = 0; c < 8; c++) { s[c] = 0.0f; q[c] = 0.0f; }

#pragma unroll
    for (int k = 0; k < ST_CHUNKS; k++) {
        int b = k & 1, parity = (k >> 1) & 1;
        asm volatile(
            "{\n\t"
            ".reg .pred p;\n\t"
            "WAITS_%=:\n\t"
            "mbarrier.try_wait.parity.acquire.cta.shared::cta.b64 p, [%0], %1;\n\t"
            "@!p bra WAITS_%=;\n\t"
            "}"
            :: "r"(mb[b]), "r"(parity) : "memory");
        const float4* sv = (const float4*)s_buf[b];
        float4 a0 = sv[tid * 2], b0 = sv[tid * 2 + 1];
        float4 a1 = sv[(tid + 256) * 2], b1 = sv[(tid + 256) * 2 + 1];
        s[0] += a0.x + a1.x; q[0] = fmaf(a0.x, a0.x, fmaf(a1.x, a1.x, q[0]));
        s[1] += a0.y + a1.y; q[1] = fmaf(a0.y, a0.y, fmaf(a1.y, a1.y, q[1]));
        s[2] += a0.z + a1.z; q[2] = fmaf(a0.z, a0.z, fmaf(a1.z, a1.z, q[2]));
        s[3] += a0.w + a1.w; q[3] = fmaf(a0.w, a0.w, fmaf(a1.w, a1.w, q[3]));
        s[4] += b0.x + b1.x; q[4] = fmaf(b0.x, b0.x, fmaf(b1.x, b1.x, q[4]));
        s[5] += b0.y + b1.y; q[5] = fmaf(b0.y, b0.y, fmaf(b1.y, b1.y, q[5]));
        s[6] += b0.z + b1.z; q[6] = fmaf(b0.z, b0.z, fmaf(b1.z, b1.z, q[6]));
        s[7] += b0.w + b1.w; q[7] = fmaf(b0.w, b0.w, fmaf(b1.w, b1.w, q[7]));
        __syncthreads();                               // buffer fully consumed
        if (tid == 0 && k + 2 < ST_CHUNKS) ST_COPY(k + 2);
    }

    // transpose-reduce (reuse the 32KB buffer area, rows of 264 floats)
    float* st = (float*)s_buf;
#pragma unroll
    for (int c = 0; c < 8; c++) {
        st[c * 264 + tid] = s[c];
        st[(8 + c) * 264 + tid] = q[c];
    }
    __syncthreads();
    {
        int w = tid >> 5, lane = tid & 31;
#pragma unroll
        for (int h = 0; h < 2; h++) {
            int c = 2 * w + h;
            const float4* row = (const float4*)(st + c * 264);
            float4 a = row[lane];
            float4 b = row[lane + 32];
            float p = ((a.x + a.y) + (a.z + a.w)) + ((b.x + b.y) + (b.z + b.w));
#pragma unroll
            for (int o = 16; o > 0; o >>= 1)
                p += __shfl_xor_sync(0xffffffffu, p, o);
            if (lane == 0) g_partials[cta * 16 + c] = p;
        }
    }

    // ---- ticket: last CTA performs the fold ----
    __shared__ unsigned int s_last;
    __threadfence();
    if (tid == 0) s_last = (atomicAdd(&g_ticket, 1u) == (unsigned)(gridDim.x - 1));
    __syncthreads();
    if (!s_last) return;

    __shared__ float s1[256];
    __shared__ float totals[16];
    __shared__ float scale[8], shift[8];
    {   // 16 cols x 16 chunks of 32; 8 independent accumulators (MLP)
        int col = tid & 15, chunk = tid >> 4;
        const float* p = g_partials + (chunk * 32) * 16 + col;
        float a0 = 0, a1 = 0, a2 = 0, a3 = 0, a4 = 0, a5 = 0, a6 = 0, a7 = 0;
#pragma unroll
        for (int b = 0; b < 32; b += 8) {
            a0 += p[(b + 0) * 16]; a1 += p[(b + 1) * 16];
            a2 += p[(b + 2) * 16]; a3 += p[(b + 3) * 16];
            a4 += p[(b + 4) * 16]; a5 += p[(b + 5) * 16];
            a6 += p[(b + 6) * 16]; a7 += p[(b + 7) * 16];
        }
        s1[col * 16 + chunk] = ((a0 + a1) + (a2 + a3)) + ((a4 + a5) + (a6 + a7));
    }
    __syncthreads();
    if (tid < 16) {
        float acc = 0.0f;
#pragma unroll
        for (int k = 0; k < 16; k++) acc += s1[tid * 16 + k];
        totals[tid] = acc;
    }
    __syncthreads();
    if (tid < 8) {
        float mu = totals[tid] * invB;
        float var = totals[8 + tid] * invB - mu * mu;
        float sc = bn_g[tid] * rsqrtf(var + 1e-5f);
        scale[tid] = sc;
        shift[tid] = bn_b[tid] - mu * sc;
    }
    __syncthreads();

    // folded first layer, layout B
    if (tid < 16) {
        float v = b_fm[tid];
#pragma unroll
        for (int i = 0; i < 8; i++) v += shift[i] * w_fm[i * 16 + tid];
        g_w[FM_B + tid] = make_float2(v, v);
    }
    if (tid < 128) {
        int j = tid >> 3, i = tid & 7;
        float v = scale[i] * w_fm[i * 16 + j];
        g_w[FM_W + j * 8 + i] = make_float2(v, v);
    }
    for (int idx = tid; idx < 256; idx += NT_STATS) {  // c1 16->16
        int j = idx >> 4, i = idx & 15;
        float v = w_c1[i * 16 + j];
        g_w[C1_W + j * 16 + i] = make_float2(v, v);
    }
    if (tid < 16) { float v = b_c1[tid]; g_w[C1_B + tid] = make_float2(v, v); }
    if (tid < 192) {                                   // p1 16->12
        int j = tid >> 4, i = tid & 15;
        float v = w_p1[i * 12 + j];
        g_w[P1_W + j * 16 + i] = make_float2(v, v);
    }
    if (tid < 12) { float v = b_p1[tid]; g_w[P1_B + tid] = make_float2(v, v); }
    if (tid < 96) {                                    // c2 12->8
        int j = tid / 12, i = tid % 12;
        float v = w_c2[i * 8 + j];
        g_w[C2_W + j * 12 + i] = make_float2(v, v);
    }
    if (tid < 8) { float v = b_c2[tid]; g_w[C2_B + tid] = make_float2(v, v); }
    if (tid < 32) {                                    // p2 8->4
        int j = tid >> 3, i = tid & 7;
        float v = w_p2[i * 4 + j];
        g_w[P2_W + j * 8 + i] = make_float2(v, v);
    }
    if (tid < 4) { float v = b_p2[tid]; g_w[P2_B + tid] = make_float2(v, v); }
    if (tid < 16) {                                    // c3 4->4
        int j = tid >> 2, i = tid & 3;
        float v = w_c3[i * 4 + j];
        g_w[C3_W + j * 4 + i] = make_float2(v, v);
    }
    if (tid < 4) { float v = b_c3[tid]; g_w[C3_B + tid] = make_float2(v, v); }
    if (tid < 16) {                                    // r 4->4
        int j = tid >> 2, i = tid & 3;
        float v = w_r[i * 4 + j];
        g_w[R_W + j * 4 + i] = make_float2(v, v);
    }
    if (tid < 4) { float v = b_r[tid]; g_w[R_B + tid] = make_float2(v, v); }
    if (tid < 4) { float v = w_h[tid]; g_w[H_W + tid] = make_float2(v, v); }
    if (tid == 0) { float v = b_h[0]; g_w[H_B] = make_float2(v, v); }
    __syncthreads();
    if (tid == 0) g_ticket = 0;                        // reset for next replay
}

// ------------------------------- kernel C: main ----------------------------
__global__ void __launch_bounds__(NT_MAIN) k_main(const float* __restrict__ x,
                                                  float* __restrict__ out,
                                                  int nrows) {
    int t = blockIdx.x * NT_MAIN + threadIdx.x;
    long base = (long)t * 4;                          // 4 rows / thread
    if (base >= nrows) return;

    const float4* xv = (const float4*)(x + base * 8);
    float4 r0a = xv[0], r0b = xv[1];
    float4 r1a = xv[2], r1b = xv[3];
    float4 r2a = xv[4], r2b = xv[5];
    float4 r3a = xv[6], r3b = xv[7];

    u64 A0[16], A1[16], B0[16], B1[16];
    A0[0] = pk2(r0a.x, r1a.x); A1[0] = pk2(r2a.x, r3a.x);
    A0[1] = pk2(r0a.y, r1a.y); A1[1] = pk2(r2a.y, r3a.y);
    A0[2] = pk2(r0a.z, r1a.z); A1[2] = pk2(r2a.z, r3a.z);
    A0[3] = pk2(r0a.w, r1a.w); A1[3] = pk2(r2a.w, r3a.w);
    A0[4] = pk2(r0b.x, r1b.x); A1[4] = pk2(r2b.x, r3b.x);
    A0[5] = pk2(r0b.y, r1b.y); A1[5] = pk2(r2b.y, r3b.y);
    A0[6] = pk2(r0b.z, r1b.z); A1[6] = pk2(r2b.z, r3b.z);
    A0[7] = pk2(r0b.w, r1b.w); A1[7] = pk2(r2b.w, r3b.w);

    layer2C<8, 16, FM_B, FM_W, true>(A0, A1, B0, B1);   // feature_map
    layer2C<16, 16, C1_B, C1_W, true>(B0, B1, A0, A1);  // conv1
    layer2C<16, 12, P1_B, P1_W, true>(A0, A1, B0, B1);  // pool1
    layer2C<12, 8, C2_B, C2_W, true>(B0, B1, A0, A1);   // conv2
    layer2C<8, 4, P2_B, P2_W, true>(A0, A1, B0, B1);    // pool2
    layer2C<4, 4, C3_B, C3_W, true>(B0, B1, A0, A1);    // conv3
    layer2C<4, 4, R_B, R_W, false>(A0, A1, B0, B1);     // residual pre-relu
#pragma unroll
    for (int j = 0; j < 4; j++) {
        A0[j] = fadd2(A0[j], relu2(B0[j]));
        A1[j] = fadd2(A1[j], relu2(B1[j]));
    }

    // head [4->1], sigmoid(z) = 0.5*tanh(0.5z)+0.5
    const u64* cw = (const u64*)c_w;
    u64 acc0 = cw[H_B], acc1 = acc0;
#pragma unroll
    for (int i = 0; i < 4; i++) {
        u64 w = cw[H_W + i];
        acc0 = ffma2(A0[i], w, acc0);
        acc1 = ffma2(A1[i], w, acc1);
    }
    float z0, z1, z2, z3;
    upk2(acc0, z0, z1);
    upk2(acc1, z2, z3);
    float4 o;
    o.x = fmaf(0.5f, tanh_ap(0.5f * z0), 0.5f);
    o.y = fmaf(0.5f, tanh_ap(0.5f * z1), 0.5f);
    o.z = fmaf(0.5f, tanh_ap(0.5f * z2), 0.5f);
    o.w = fmaf(0.5f, tanh_ap(0.5f * z3), 0.5f);
    ((float4*)out)[t] = o;
}

// ------------------------------- launch ------------------------------------
extern "C" void kernel_launch(void* const* d_in, const int* in_sizes, int n_in,
                              void* d_out, int out_size) {
    const float* x    = (const float*)d_in[0];
    const float* bn_g = (const float*)d_in[1];
    const float* bn_b = (const float*)d_in[2];
    const float* w_fm = (const float*)d_in[3];
    const float* b_fm = (const float*)d_in[4];
    const float* w_c1 = (const float*)d_in[5];
    const float* b_c1 = (const float*)d_in[6];
    const float* w_p1 = (const float*)d_in[7];
    const float* b_p1 = (const float*)d_in[8];
    const float* w_c2 = (const float*)d_in[9];
    const float* b_c2 = (const float*)d_in[10];
    const float* w_p2 = (const float*)d_in[11];
    const float* b_p2 = (const float*)d_in[12];
    const float* w_c3 = (const float*)d_in[13];
    const float* b_c3 = (const float*)d_in[14];
    const float* w_r  = (const float*)d_in[15];
    const float* b_r  = (const float*)d_in[16];
    const float* w_h  = (const float*)d_in[17];
    const float* b_h  = (const float*)d_in[18];
    float* out = (float*)d_out;

    int nrows = in_sizes[0] / 8;                      // 1048576

    k_statsfold<<<ST_GRID, NT_STATS>>>(x, bn_g, bn_b, w_fm, b_fm,
                                       w_c1, b_c1, w_p1, b_p1, w_c2, b_c2,
                                       w_p2, b_p2, w_c3, b_c3, w_r, b_r,
                                       w_h, b_h, 1.0f / (float)nrows);
    void* gw_addr = nullptr;
    cudaGetSymbolAddress(&gw_addr, g_w);
    cudaMemcpyToSymbolAsync(c_w, gw_addr, U_TOTAL * sizeof(float2), 0,
                            cudaMemcpyDeviceToDevice, 0);
    k_main<<<(nrows / 4) / NT_MAIN, NT_MAIN>>>(x, out, nrows);
}

// round 17
// speedup vs baseline: 1.0818x; 1.0019x over previous
#include <cuda_runtime.h>
#include <cuda_bf16.h>

// ---------------------------------------------------------------------------
// QCNNHybrid R16 (= R15, the 49.8us config, with NT_MAIN 128 -> 64):
//  k_statsfold : 512 CTAs x 4 chunks of 16KB, double-buffered cp.async.bulk;
//                SMEM-transpose reduction; LAST CTA (ticket) folds BN.
//  memcpy      : g_w -> __constant__ c_w (graph node).
//  k_main      : frozen R10 core; block=64 kills register-quantization ->
//                7 blocks/SM = 14 warps (was 12). No sync/smem in kernel,
//                so block size is semantically free.
// ---------------------------------------------------------------------------

#define ST_GRID    512
#define ST_CHUNKS  4
#define NT_STATS   256
#define NT_MAIN    64

__device__ float g_partials[ST_GRID * 16];
__device__ unsigned int g_ticket;    // zero-init; self-resets each replay

// layout B (u64 units): per layer [bias x DOUT][weights j-major: DOUT x DIN]
#define FM_B 0
#define FM_W 16     // 16 + 128 = 144
#define C1_B 144
#define C1_W 160    // + 256 = 416
#define P1_B 416
#define P1_W 428    // + 192 = 620
#define C2_B 620
#define C2_W 628    // + 96 = 724
#define P2_B 724
#define P2_W 728    // + 32 = 760
#define C3_B 760
#define C3_W 764    // + 16 = 780
#define R_B  780
#define R_W  784    // + 16 = 800
#define H_B  800
#define H_W  801    // + 4 = 805
#define U_TOTAL 805
__device__ float2 g_w[U_TOTAL];
__constant__ __align__(16) float2 c_w[U_TOTAL + 1];

typedef unsigned long long u64;

// ------------------------------- f32x2 helpers -----------------------------
__device__ __forceinline__ u64 pk2(float a, float b) {
    u64 r;
    asm("mov.b64 %0,{%1,%2};" : "=l"(r) : "f"(a), "f"(b));
    return r;
}
__device__ __forceinline__ void upk2(u64 v, float& a, float& b) {
    asm("mov.b64 {%0,%1},%2;" : "=f"(a), "=f"(b) : "l"(v));
}
__device__ __forceinline__ u64 ffma2(u64 a, u64 b, u64 c) {
    u64 d;
    asm("fma.rn.f32x2 %0,%1,%2,%3;" : "=l"(d) : "l"(a), "l"(b), "l"(c));
    return d;
}
__device__ __forceinline__ u64 fadd2(u64 a, u64 b) {
    u64 d;
    asm("add.rn.f32x2 %0,%1,%2;" : "=l"(d) : "l"(a), "l"(b));
    return d;
}
__device__ __forceinline__ float tanh_ap(float x) {
    float y;
    asm("tanh.approx.f32 %0,%1;" : "=f"(y) : "f"(x));
    return y;
}
__device__ __forceinline__ u64 tanh2(u64 v) {
    float a, b;
    upk2(v, a, b);
    return pk2(tanh_ap(a), tanh_ap(b));
}
__device__ __forceinline__ u64 relu2(u64 v) {
    float a, b;
    upk2(v, a, b);
    return pk2(fmaxf(a, 0.0f), fmaxf(b, 0.0f));
}

// dense layer on two packs (4 rows); weights via vectorized constant loads.
template <int DIN, int DOUT, int BB, int WB, bool ACT>
__device__ __forceinline__ void layer2C(const u64* __restrict__ a0,
                                        const u64* __restrict__ a1,
                                        u64* __restrict__ o0,
                                        u64* __restrict__ o1) {
    const u64* cw = (const u64*)c_w;
#pragma unroll
    for (int j = 0; j < DOUT; j++) {
        u64 acc0 = cw[BB + j];                        // duplicated bias
        u64 acc1 = acc0;
#pragma unroll
        for (int i = 0; i < DIN; i += 2) {
            ulonglong2 w = *(const ulonglong2*)(cw + WB + j * DIN + i);
            acc0 = ffma2(a0[i], w.x, acc0);
            acc1 = ffma2(a1[i], w.x, acc1);
            acc0 = ffma2(a0[i + 1], w.y, acc0);
            acc1 = ffma2(a1[i + 1], w.y, acc1);
        }
        if (ACT) { acc0 = tanh2(acc0); acc1 = tanh2(acc1); }
        o0[j] = acc0;
        o1[j] = acc1;
    }
}

// --------------------------- kernel A: stats + fold ------------------------
__global__ void __launch_bounds__(NT_STATS) k_statsfold(
    const float* __restrict__ x,
    const float* __restrict__ bn_g, const float* __restrict__ bn_b,
    const float* __restrict__ w_fm, const float* __restrict__ b_fm,
    const float* __restrict__ w_c1, const float* __restrict__ b_c1,
    const float* __restrict__ w_p1, const float* __restrict__ b_p1,
    const float* __restrict__ w_c2, const float* __restrict__ b_c2,
    const float* __restrict__ w_p2, const float* __restrict__ b_p2,
    const float* __restrict__ w_c3, const float* __restrict__ b_c3,
    const float* __restrict__ w_r,  const float* __restrict__ b_r,
    const float* __restrict__ w_h,  const float* __restrict__ b_h,
    float invB) {
    __shared__ __align__(16) float s_buf[2][4096];    // 2 x 16KB
    __shared__ __align__(8) u64 s_mbar[2];
    int tid = threadIdx.x;
    int cta = blockIdx.x;

    unsigned mb[2] = { (unsigned)__cvta_generic_to_shared(&s_mbar[0]),
                       (unsigned)__cvta_generic_to_shared(&s_mbar[1]) };
    unsigned sb[2] = { (unsigned)__cvta_generic_to_shared(s_buf[0]),
                       (unsigned)__cvta_generic_to_shared(s_buf[1]) };
    if (tid == 0) {
        asm volatile("mbarrier.init.shared.b64 [%0], 1;" :: "r"(mb[0]) : "memory");
        asm volatile("mbarrier.init.shared.b64 [%0], 1;" :: "r"(mb[1]) : "memory");
        asm volatile("fence.proxy.async.shared::cta;" ::: "memory");
    }
    __syncthreads();

#define ST_COPY(k)                                                             \
    do {                                                                       \
        int _b = (k) & 1;                                                      \
        const char* _src =                                                     \
            (const char*)x + ((size_t)cta * ST_CHUNKS + (k)) * 16384;          \
        asm volatile("mbarrier.arrive.expect_tx.shared.b64 _, [%0], %1;"       \
                     :: "r"(mb[_b]), "r"(16384u) : "memory");                  \
        asm volatile(                                                          \
            "cp.async.bulk.shared::cluster.global.mbarrier::complete_tx::bytes "\
            "[%0], [%1], %2, [%3];"                                            \
            :: "r"(sb[_b]), "l"(_src), "r"(16384u), "r"(mb[_b]) : "memory");   \
    } while (0)

    if (tid == 0) { ST_COPY(0); ST_COPY(1); }

    float s[8], q[8];
#pragma unroll
    for (int c = 0; c < 8; c++) { s[c] = 0.0f; q[c] = 0.0f; }

#pragma unroll
    for (int k = 0; k < ST_CHUNKS; k++) {
        int b = k & 1, parity = (k >> 1) & 1;
        asm volatile(
            "{\n\t"
            ".reg .pred p;\n\t"
            "WAITS_%=:\n\t"
            "mbarrier.try_wait.parity.acquire.cta.shared::cta.b64 p, [%0], %1;\n\t"
            "@!p bra WAITS_%=;\n\t"
            "}"
            :: "r"(mb[b]), "r"(parity) : "memory");
        const float4* sv = (const float4*)s_buf[b];
        float4 a0 = sv[tid * 2], b0 = sv[tid * 2 + 1];
        float4 a1 = sv[(tid + 256) * 2], b1 = sv[(tid + 256) * 2 + 1];
        s[0] += a0.x + a1.x; q[0] = fmaf(a0.x, a0.x, fmaf(a1.x, a1.x, q[0]));
        s[1] += a0.y + a1.y; q[1] = fmaf(a0.y, a0.y, fmaf(a1.y, a1.y, q[1]));
        s[2] += a0.z + a1.z; q[2] = fmaf(a0.z, a0.z, fmaf(a1.z, a1.z, q[2]));
        s[3] += a0.w + a1.w; q[3] = fmaf(a0.w, a0.w, fmaf(a1.w, a1.w, q[3]));
        s[4] += b0.x + b1.x; q[4] = fmaf(b0.x, b0.x, fmaf(b1.x, b1.x, q[4]));
        s[5] += b0.y + b1.y; q[5] = fmaf(b0.y, b0.y, fmaf(b1.y, b1.y, q[5]));
        s[6] += b0.z + b1.z; q[6] = fmaf(b0.z, b0.z, fmaf(b1.z, b1.z, q[6]));
        s[7] += b0.w + b1.w; q[7] = fmaf(b0.w, b0.w, fmaf(b1.w, b1.w, q[7]));
        __syncthreads();                               // buffer fully consumed
        if (tid == 0 && k + 2 < ST_CHUNKS) ST_COPY(k + 2);
    }

    // transpose-reduce (reuse the 32KB buffer area, rows of 264 floats)
    float* st = (float*)s_buf;
#pragma unroll
    for (int c = 0; c < 8; c++) {
        st[c * 264 + tid] = s[c];
        st[(8 + c) * 264 + tid] = q[c];
    }
    __syncthreads();
    {
        int w = tid >> 5, lane = tid & 31;
#pragma unroll
        for (int h = 0; h < 2; h++) {
            int c = 2 * w + h;
            const float4* row = (const float4*)(st + c * 264);
            float4 a = row[lane];
            float4 b = row[lane + 32];
            float p = ((a.x + a.y) + (a.z + a.w)) + ((b.x + b.y) + (b.z + b.w));
#pragma unroll
            for (int o = 16; o > 0; o >>= 1)
                p += __shfl_xor_sync(0xffffffffu, p, o);
            if (lane == 0) g_partials[cta * 16 + c] = p;
        }
    }

    // ---- ticket: last CTA performs the fold ----
    __shared__ unsigned int s_last;
    __threadfence();
    if (tid == 0) s_last = (atomicAdd(&g_ticket, 1u) == (unsigned)(gridDim.x - 1));
    __syncthreads();
    if (!s_last) return;

    __shared__ float s1[256];
    __shared__ float totals[16];
    __shared__ float scale[8], shift[8];
    {   // 16 cols x 16 chunks of 32; 8 independent accumulators (MLP)
        int col = tid & 15, chunk = tid >> 4;
        const float* p = g_partials + (chunk * 32) * 16 + col;
        float a0 = 0, a1 = 0, a2 = 0, a3 = 0, a4 = 0, a5 = 0, a6 = 0, a7 = 0;
#pragma unroll
        for (int b = 0; b < 32; b += 8) {
            a0 += p[(b + 0) * 16]; a1 += p[(b + 1) * 16];
            a2 += p[(b + 2) * 16]; a3 += p[(b + 3) * 16];
            a4 += p[(b + 4) * 16]; a5 += p[(b + 5) * 16];
            a6 += p[(b + 6) * 16]; a7 += p[(b + 7) * 16];
        }
        s1[col * 16 + chunk] = ((a0 + a1) + (a2 + a3)) + ((a4 + a5) + (a6 + a7));
    }
    __syncthreads();
    if (tid < 16) {
        float acc = 0.0f;
#pragma unroll
        for (int k = 0; k < 16; k++) acc += s1[tid * 16 + k];
        totals[tid] = acc;
    }
    __syncthreads();
    if (tid < 8) {
        float mu = totals[tid] * invB;
        float var = totals[8 + tid] * invB - mu * mu;
        float sc = bn_g[tid] * rsqrtf(var + 1e-5f);
        scale[tid] = sc;
        shift[tid] = bn_b[tid] - mu * sc;
    }
    __syncthreads();

    // folded first layer, layout B
    if (tid < 16) {
        float v = b_fm[tid];
#pragma unroll
        for (int i = 0; i < 8; i++) v += shift[i] * w_fm[i * 16 + tid];
        g_w[FM_B + tid] = make_float2(v, v);
    }
    if (tid < 128) {
        int j = tid >> 3, i = tid & 7;
        float v = scale[i] * w_fm[i * 16 + j];
        g_w[FM_W + j * 8 + i] = make_float2(v, v);
    }
    for (int idx = tid; idx < 256; idx += NT_STATS) {  // c1 16->16
        int j = idx >> 4, i = idx & 15;
        float v = w_c1[i * 16 + j];
        g_w[C1_W + j * 16 + i] = make_float2(v, v);
    }
    if (tid < 16) { float v = b_c1[tid]; g_w[C1_B + tid] = make_float2(v, v); }
    if (tid < 192) {                                   // p1 16->12
        int j = tid >> 4, i = tid & 15;
        float v = w_p1[i * 12 + j];
        g_w[P1_W + j * 16 + i] = make_float2(v, v);
    }
    if (tid < 12) { float v = b_p1[tid]; g_w[P1_B + tid] = make_float2(v, v); }
    if (tid < 96) {                                    // c2 12->8
        int j = tid / 12, i = tid % 12;
        float v = w_c2[i * 8 + j];
        g_w[C2_W + j * 12 + i] = make_float2(v, v);
    }
    if (tid < 8) { float v = b_c2[tid]; g_w[C2_B + tid] = make_float2(v, v); }
    if (tid < 32) {                                    // p2 8->4
        int j = tid >> 3, i = tid & 7;
        float v = w_p2[i * 4 + j];
        g_w[P2_W + j * 8 + i] = make_float2(v, v);
    }
    if (tid < 4) { float v = b_p2[tid]; g_w[P2_B + tid] = make_float2(v, v); }
    if (tid < 16) {                                    // c3 4->4
        int j = tid >> 2, i = tid & 3;
        float v = w_c3[i * 4 + j];
        g_w[C3_W + j * 4 + i] = make_float2(v, v);
    }
    if (tid < 4) { float v = b_c3[tid]; g_w[C3_B + tid] = make_float2(v, v); }
    if (tid < 16) {                                    // r 4->4
        int j = tid >> 2, i = tid & 3;
        float v = w_r[i * 4 + j];
        g_w[R_W + j * 4 + i] = make_float2(v, v);
    }
    if (tid < 4) { float v = b_r[tid]; g_w[R_B + tid] = make_float2(v, v); }
    if (tid < 4) { float v = w_h[tid]; g_w[H_W + tid] = make_float2(v, v); }
    if (tid == 0) { float v = b_h[0]; g_w[H_B] = make_float2(v, v); }
    __syncthreads();
    if (tid == 0) g_ticket = 0;                        // reset for next replay
}

// ------------------------------- kernel C: main ----------------------------
__global__ void __launch_bounds__(NT_MAIN) k_main(const float* __restrict__ x,
                                                  float* __restrict__ out,
                                                  int nrows) {
    int t = blockIdx.x * NT_MAIN + threadIdx.x;
    long base = (long)t * 4;                          // 4 rows / thread
    if (base >= nrows) return;

    const float4* xv = (const float4*)(x + base * 8);
    float4 r0a = xv[0], r0b = xv[1];
    float4 r1a = xv[2], r1b = xv[3];
    float4 r2a = xv[4], r2b = xv[5];
    float4 r3a = xv[6], r3b = xv[7];

    u64 A0[16], A1[16], B0[16], B1[16];
    A0[0] = pk2(r0a.x, r1a.x); A1[0] = pk2(r2a.x, r3a.x);
    A0[1] = pk2(r0a.y, r1a.y); A1[1] = pk2(r2a.y, r3a.y);
    A0[2] = pk2(r0a.z, r1a.z); A1[2] = pk2(r2a.z, r3a.z);
    A0[3] = pk2(r0a.w, r1a.w); A1[3] = pk2(r2a.w, r3a.w);
    A0[4] = pk2(r0b.x, r1b.x); A1[4] = pk2(r2b.x, r3b.x);
    A0[5] = pk2(r0b.y, r1b.y); A1[5] = pk2(r2b.y, r3b.y);
    A0[6] = pk2(r0b.z, r1b.z); A1[6] = pk2(r2b.z, r3b.z);
    A0[7] = pk2(r0b.w, r1b.w); A1[7] = pk2(r2b.w, r3b.w);

    layer2C<8, 16, FM_B, FM_W, true>(A0, A1, B0, B1);   // feature_map
    layer2C<16, 16, C1_B, C1_W, true>(B0, B1, A0, A1);  // conv1
    layer2C<16, 12, P1_B, P1_W, true>(A0, A1, B0, B1);  // pool1
    layer2C<12, 8, C2_B, C2_W, true>(B0, B1, A0, A1);   // conv2
    layer2C<8, 4, P2_B, P2_W, true>(A0, A1, B0, B1);    // pool2
    layer2C<4, 4, C3_B, C3_W, true>(B0, B1, A0, A1);    // conv3
    layer2C<4, 4, R_B, R_W, false>(A0, A1, B0, B1);     // residual pre-relu
#pragma unroll
    for (int j = 0; j < 4; j++) {
        A0[j] = fadd2(A0[j], relu2(B0[j]));
        A1[j] = fadd2(A1[j], relu2(B1[j]));
    }

    // head [4->1], sigmoid(z) = 0.5*tanh(0.5z)+0.5
    const u64* cw = (const u64*)c_w;
    u64 acc0 = cw[H_B], acc1 = acc0;
#pragma unroll
    for (int i = 0; i < 4; i++) {
        u64 w = cw[H_W + i];
        acc0 = ffma2(A0[i], w, acc0);
        acc1 = ffma2(A1[i], w, acc1);
    }
    float z0, z1, z2, z3;
    upk2(acc0, z0, z1);
    upk2(acc1, z2, z3);
    float4 o;
    o.x = fmaf(0.5f, tanh_ap(0.5f * z0), 0.5f);
    o.y = fmaf(0.5f, tanh_ap(0.5f * z1), 0.5f);
    o.z = fmaf(0.5f, tanh_ap(0.5f * z2), 0.5f);
    o.w = fmaf(0.5f, tanh_ap(0.5f * z3), 0.5f);
    ((float4*)out)[t] = o;
}

// ------------------------------- launch ------------------------------------
extern "C" void kernel_launch(void* const* d_in, const int* in_sizes, int n_in,
                              void* d_out, int out_size) {
    const float* x    = (const float*)d_in[0];
    const float* bn_g = (const float*)d_in[1];
    const float* bn_b = (const float*)d_in[2];
    const float* w_fm = (const float*)d_in[3];
    const float* b_fm = (const float*)d_in[4];
    const float* w_c1 = (const float*)d_in[5];
    const float* b_c1 = (const float*)d_in[6];
    const float* w_p1 = (const float*)d_in[7];
    const float* b_p1 = (const float*)d_in[8];
    const float* w_c2 = (const float*)d_in[9];
    const float* b_c2 = (const float*)d_in[10];
    const float* w_p2 = (const float*)d_in[11];
    const float* b_p2 = (const float*)d_in[12];
    const float* w_c3 = (const float*)d_in[13];
    const float* b_c3 = (const float*)d_in[14];
    const float* w_r  = (const float*)d_in[15];
    const float* b_r  = (const float*)d_in[16];
    const float* w_h  = (const float*)d_in[17];
    const float* b_h  = (const float*)d_in[18];
    float* out = (float*)d_out;

    int nrows = in_sizes[0] / 8;                      // 1048576

    k_statsfold<<<ST_GRID, NT_STATS>>>(x, bn_g, bn_b, w_fm, b_fm,
                                       w_c1, b_c1, w_p1, b_p1, w_c2, b_c2,
                                       w_p2, b_p2, w_c3, b_c3, w_r, b_r,
                                       w_h, b_h, 1.0f / (float)nrows);
    void* gw_addr = nullptr;
    cudaGetSymbolAddress(&gw_addr, g_w);
    cudaMemcpyToSymbolAsync(c_w, gw_addr, U_TOTAL * sizeof(float2), 0,
                            cudaMemcpyDeviceToDevice, 0);
    k_main<<<(nrows / 4) / NT_MAIN, NT_MAIN>>>(x, out, nrows);
}